// round 1
// baseline (speedup 1.0000x reference)
#include <cuda_runtime.h>

#define B_    4
#define CIN   256
#define HH    64
#define WW    64
#define COUT  256
#define K2    9
#define NPIX  4096          // per batch (64*64)
#define KTOT  (K2*CIN)      // 2304
#define KC    16            // K-chunk
#define PT    32            // pixel tile
#define CROW  36            // padded Csm row (bank-conflict-free, 16B-aligned)

// ---- scratch (static device globals; no allocation in kernel_launch) ----
__device__ __align__(16) float  g_xnhwc[B_ * NPIX * CIN];   // 16.8 MB  x in NHWC
__device__ __align__(16) float  g_wt[KTOT * COUT];          // 2.36 MB  W as [k2*256+ci][co]
__device__ __align__(16) int4   g_sidx[B_ * K2 * NPIX];     // corner base offsets (elem, ch0)
__device__ __align__(16) float4 g_swt [B_ * K2 * NPIX];     // corner weights (bilinear*mask*valid)

// ---------------------------------------------------------------------------
// Prep 1: NCHW -> NHWC transpose of x (smem-tiled, coalesced both sides)
// grid (128, 8, 4), block (32, 8)
// ---------------------------------------------------------------------------
__global__ void k_prep_x(const float* __restrict__ x) {
    __shared__ float tile[32][33];
    int b  = blockIdx.z;
    int p0 = blockIdx.x * 32;
    int c0 = blockIdx.y * 32;
    int tx = threadIdx.x, ty = threadIdx.y;
#pragma unroll
    for (int i = ty; i < 32; i += 8)
        tile[i][tx] = x[(b * CIN + c0 + i) * NPIX + p0 + tx];
    __syncthreads();
#pragma unroll
    for (int i = ty; i < 32; i += 8)
        g_xnhwc[(b * NPIX + p0 + i) * CIN + c0 + tx] = tile[tx][i];
}

// ---------------------------------------------------------------------------
// Prep 2: weight [co][ci][ky][kx] -> Wt[(k2*256+ci)][co]   (grid KTOT, 256 thr)
// ---------------------------------------------------------------------------
__global__ void k_prep_w(const float* __restrict__ w) {
    int k  = blockIdx.x;          // 0..2303
    int co = threadIdx.x;         // 0..255
    int k2 = k >> 8;
    int ci = k & 255;
    g_wt[k * COUT + co] = w[(co * CIN + ci) * K2 + k2];
}

// ---------------------------------------------------------------------------
// Prep 3: sampling params per (b, k2, pixel): 4 corner offsets + folded weights
// grid 576, block 256  (4*9*4096 threads)
// ---------------------------------------------------------------------------
__global__ void k_prep_params(const float* __restrict__ offset,
                              const float* __restrict__ mask) {
    int t = blockIdx.x * blockDim.x + threadIdx.x;     // [0, 147456)
    int b  = t / (K2 * NPIX);
    int r  = t - b * (K2 * NPIX);
    int k2 = r >> 12;
    int p  = r & (NPIX - 1);
    int ho = p >> 6, wo = p & 63;
    int ky = k2 / 3, kx = k2 - ky * 3;

    float dy_off = offset[(b * 2 * K2 + 2 * k2    ) * NPIX + p];
    float dx_off = offset[(b * 2 * K2 + 2 * k2 + 1) * NPIX + p];
    float m      = mask  [(b * K2 + k2) * NPIX + p];

    float yf = (float)(ky + ho - 1) + dy_off;   // stride 1, pad 1
    float xf = (float)(kx + wo - 1) + dx_off;
    float y0f = floorf(yf), x0f = floorf(xf);
    float dy = yf - y0f,    dx = xf - x0f;
    int y0 = (int)y0f, x0 = (int)x0f;
    int y1 = y0 + 1,   x1 = x0 + 1;

    float w00 = (1.f - dy) * (1.f - dx) * m;
    float w01 = (1.f - dy) * dx * m;
    float w10 = dy * (1.f - dx) * m;
    float w11 = dy * dx * m;

    bool vy0 = (y0 >= 0) & (y0 < HH);
    bool vy1 = (y1 >= 0) & (y1 < HH);
    bool vx0 = (x0 >= 0) & (x0 < WW);
    bool vx1 = (x1 >= 0) & (x1 < WW);
    if (!(vy0 & vx0)) w00 = 0.f;
    if (!(vy0 & vx1)) w01 = 0.f;
    if (!(vy1 & vx0)) w10 = 0.f;
    if (!(vy1 & vx1)) w11 = 0.f;

    int y0c = min(max(y0, 0), HH - 1), y1c = min(max(y1, 0), HH - 1);
    int x0c = min(max(x0, 0), WW - 1), x1c = min(max(x1, 0), WW - 1);
    int base = b * NPIX;
    g_sidx[t] = make_int4((base + y0c * WW + x0c) * CIN,
                          (base + y0c * WW + x1c) * CIN,
                          (base + y1c * WW + x0c) * CIN,
                          (base + y1c * WW + x1c) * CIN);
    g_swt[t]  = make_float4(w00, w01, w10, w11);
}

// ---------------------------------------------------------------------------
// Main fused deformable-conv implicit GEMM.
// Tile: 256 output channels x 32 pixels per block. K loop: 9 kernel points x
// 16-channel chunks. col chunk built in smem from coalesced NHWC gathers
// (x fully L2-resident). Per-thread register tile: 8 co x 4 px.
// grid 512 (= 4 batches * 128 pixel tiles), block 256
// ---------------------------------------------------------------------------
__global__ __launch_bounds__(256, 2)
void k_conv(const float* __restrict__ bias, float* __restrict__ out) {
    __shared__ float Wsm[KC * COUT];      // 16 KB
    __shared__ float Csm[KC * CROW];      // 2.25 KB (rows padded to 36)
    __shared__ int4   sO[PT];
    __shared__ float4 sW[PT];

    int b    = blockIdx.x >> 7;
    int tile = blockIdx.x & 127;
    int p0   = tile * PT;
    int tid  = threadIdx.x;
    int warp = tid >> 5, lane = tid & 31;
    // compute mapping: conflict-free smem reads (cg duplicated x4 in lane -> broadcast)
    int cg = (warp & 3) * 8 + (lane >> 2);   // 0..31 -> co_base = cg*8
    int pg = (warp >> 2) * 4 + (lane & 3);   // 0..7  -> px 4*pg..4*pg+3
    int co_base = cg * 8;

    float acc[8][4];
#pragma unroll
    for (int i = 0; i < 8; i++)
#pragma unroll
        for (int j = 0; j < 4; j++) acc[i][j] = 0.f;

    int ci_l = tid & 15;     // col-build mapping: 16 ci x 16 px, 2 px per thread
    int pA   = tid >> 4;

    for (int k2 = 0; k2 < K2; k2++) {
        if (tid < PT) {
            int pi = (b * K2 + k2) * NPIX + p0 + tid;
            sO[tid] = g_sidx[pi];
            sW[tid] = g_swt[pi];
        }
        const float* wsrc = g_wt + (k2 * CIN) * COUT;

        for (int c0 = 0; c0 < CIN; c0 += KC) {
            __syncthreads();   // publishes sO/sW; protects Wsm/Csm reuse
            // W chunk: one contiguous 16 KB block, coalesced float4 copy
            const float4* ws4 = (const float4*)(wsrc + c0 * COUT);
            float4* wd4 = (float4*)Wsm;
#pragma unroll
            for (int i = 0; i < 4; i++) wd4[tid + i * 256] = ws4[tid + i * 256];
            // col chunk: 4 coalesced L2-hit gathers per element
            {
                int ci = c0 + ci_l;
#pragma unroll
                for (int h = 0; h < 2; h++) {
                    int p = pA + h * 16;
                    int4  o = sO[p];
                    float4 w = sW[p];
                    float v = w.x * g_xnhwc[o.x + ci] + w.y * g_xnhwc[o.y + ci]
                            + w.z * g_xnhwc[o.z + ci] + w.w * g_xnhwc[o.w + ci];
                    Csm[ci_l * CROW + p] = v;
                }
            }
            __syncthreads();
            // 8x4 register-tile FMA: 3x LDS.128 per kk per thread, 32 FFMA
#pragma unroll
            for (int kk = 0; kk < KC; kk++) {
                float4 w0 = *(const float4*)&Wsm[kk * COUT + co_base];
                float4 w1 = *(const float4*)&Wsm[kk * COUT + co_base + 4];
                float4 cc = *(const float4*)&Csm[kk * CROW + pg * 4];
                float wv[8] = {w0.x, w0.y, w0.z, w0.w, w1.x, w1.y, w1.z, w1.w};
                float cv[4] = {cc.x, cc.y, cc.z, cc.w};
#pragma unroll
                for (int i = 0; i < 8; i++)
#pragma unroll
                    for (int j = 0; j < 4; j++)
                        acc[i][j] += wv[i] * cv[j];
            }
        }
    }
    // epilogue: + bias, write NCHW
#pragma unroll
    for (int i = 0; i < 8; i++) {
        float bv = bias[co_base + i];
        float4 o;
        o.x = acc[i][0] + bv; o.y = acc[i][1] + bv;
        o.z = acc[i][2] + bv; o.w = acc[i][3] + bv;
        *(float4*)&out[((size_t)(b * COUT + co_base + i)) * NPIX + p0 + pg * 4] = o;
    }
}

// ---------------------------------------------------------------------------
// GroupNorm(32) + ReLU, in place on d_out. One block per (b, group):
// 8 channels x 4096 px = 32768 elems.  grid 128, block 256
// ---------------------------------------------------------------------------
__global__ __launch_bounds__(256)
void k_gn(float* __restrict__ out,
          const float* __restrict__ gamma, const float* __restrict__ beta) {
    int b = blockIdx.x >> 5;
    int g = blockIdx.x & 31;
    float4* b4 = (float4*)(out + ((size_t)(b * COUT + g * 8)) * NPIX);
    int tid = threadIdx.x;

    float s = 0.f, ss = 0.f;
    for (int i = tid; i < 8192; i += 256) {
        float4 v = b4[i];
        s  += v.x + v.y + v.z + v.w;
        ss += v.x * v.x + v.y * v.y + v.z * v.z + v.w * v.w;
    }
#pragma unroll
    for (int o = 16; o; o >>= 1) {
        s  += __shfl_down_sync(0xFFFFFFFFu, s, o);
        ss += __shfl_down_sync(0xFFFFFFFFu, ss, o);
    }
    __shared__ float red[16];
    __shared__ float stats[2];
    int warp = tid >> 5, lane = tid & 31;
    if (lane == 0) { red[warp] = s; red[warp + 8] = ss; }
    __syncthreads();
    if (tid == 0) {
        float S = 0.f, SS = 0.f;
#pragma unroll
        for (int i = 0; i < 8; i++) { S += red[i]; SS += red[i + 8]; }
        float mu  = S * (1.f / 32768.f);
        float var = SS * (1.f / 32768.f) - mu * mu;
        stats[0] = mu;
        stats[1] = rsqrtf(var + 1e-5f);
    }
    __syncthreads();
    float mu = stats[0], rstd = stats[1];
    for (int i = tid; i < 8192; i += 256) {
        int c = g * 8 + (i >> 10);
        float ga = gamma[c], be = beta[c];
        float4 v = b4[i];
        v.x = fmaxf((v.x - mu) * rstd * ga + be, 0.f);
        v.y = fmaxf((v.y - mu) * rstd * ga + be, 0.f);
        v.z = fmaxf((v.z - mu) * rstd * ga + be, 0.f);
        v.w = fmaxf((v.w - mu) * rstd * ga + be, 0.f);
        b4[i] = v;
    }
}

// ---------------------------------------------------------------------------
extern "C" void kernel_launch(void* const* d_in, const int* in_sizes, int n_in,
                              void* d_out, int out_size) {
    const float* x      = (const float*)d_in[0];
    const float* offset = (const float*)d_in[1];
    const float* mask   = (const float*)d_in[2];
    const float* weight = (const float*)d_in[3];
    const float* bias   = (const float*)d_in[4];
    const float* gamma  = (const float*)d_in[5];
    const float* beta   = (const float*)d_in[6];
    float* out = (float*)d_out;

    k_prep_x<<<dim3(128, 8, 4), dim3(32, 8)>>>(x);
    k_prep_w<<<KTOT, 256>>>(weight);
    k_prep_params<<<576, 256>>>(offset, mask);
    k_conv<<<512, 256>>>(bias, out);
    k_gn<<<128, 256>>>(out, gamma, beta);
}

// round 4
// speedup vs baseline: 2.7097x; 2.7097x over previous
#include <cuda_runtime.h>
#include <cstdint>

#define B_    4
#define CIN   256
#define HH    64
#define WW    64
#define COUT  256
#define K2    9
#define NPIX  4096
#define NCHUNK 72               // 8 ci32-chunks * 9 k2, order: c32 outer, k2 inner
#define PAD   36                // floats per smem row (144B = 9*16B)

// ---------------- scratch ----------------
__device__ __align__(16) float    g_xnhwc[B_ * NPIX * CIN];   // x NHWC fp32
__device__ __align__(16) uint32_t g_wt[NCHUNK * 8192];        // W tf32: [ch][co256][k32]
__device__ __align__(16) int4     g_sidx[B_ * K2 * NPIX];
__device__ __align__(16) float4   g_swt [B_ * K2 * NPIX];

__device__ __forceinline__ uint32_t smem_u32(const void* p) {
    uint32_t a;
    asm("{ .reg .u64 t; cvta.to.shared.u64 t, %1; cvt.u32.u64 %0, t; }" : "=r"(a) : "l"(p));
    return a;
}
__device__ __forceinline__ uint32_t f2tf32(float v) {
    uint32_t t;
    asm("cvt.rna.tf32.f32 %0, %1;" : "=r"(t) : "f"(v));
    return t;
}
__device__ __forceinline__ void mma_tf32(float* c, const uint32_t* a, const uint32_t* b) {
    asm volatile("mma.sync.aligned.m16n8k8.row.col.f32.tf32.tf32.f32 "
        "{%0,%1,%2,%3}, {%4,%5,%6,%7}, {%8,%9}, {%0,%1,%2,%3};"
        : "+f"(c[0]), "+f"(c[1]), "+f"(c[2]), "+f"(c[3])
        : "r"(a[0]), "r"(a[1]), "r"(a[2]), "r"(a[3]), "r"(b[0]), "r"(b[1]));
}

// ---------------------------------------------------------------------------
// Prep 1: x NCHW -> NHWC
__global__ void k_prep_x(const float* __restrict__ x) {
    __shared__ float tile[32][33];
    int b = blockIdx.z, p0 = blockIdx.x * 32, c0 = blockIdx.y * 32;
    int tx = threadIdx.x, ty = threadIdx.y;
#pragma unroll
    for (int i = ty; i < 32; i += 8)
        tile[i][tx] = x[(b * CIN + c0 + i) * NPIX + p0 + tx];
    __syncthreads();
#pragma unroll
    for (int i = ty; i < 32; i += 8)
        g_xnhwc[(b * NPIX + p0 + i) * CIN + c0 + tx] = tile[tx][i];
}

// Prep 2: W -> tf32 chunks [ch = c32*9+k2][co][k32]
__global__ void k_prep_w(const float* __restrict__ w) {
    int ch  = blockIdx.x;
    int c32 = ch / 9, k2 = ch - c32 * 9;
    uint32_t* dst = g_wt + ch * 8192;
    for (int e = threadIdx.x; e < 8192; e += 256) {
        int r = e >> 5, j = e & 31;          // co, ci-within-chunk
        float v = w[(r * CIN + c32 * 32 + j) * K2 + k2];
        dst[r * 32 + j] = f2tf32(v);
    }
}

// Prep 3: sampling params
__global__ void k_prep_params(const float* __restrict__ offset,
                              const float* __restrict__ mask) {
    int t = blockIdx.x * blockDim.x + threadIdx.x;
    int b  = t / (K2 * NPIX);
    int r  = t - b * (K2 * NPIX);
    int k2 = r >> 12;
    int p  = r & (NPIX - 1);
    int ho = p >> 6, wo = p & 63;
    int ky = k2 / 3, kx = k2 - ky * 3;

    float dy_off = offset[(b * 2 * K2 + 2 * k2    ) * NPIX + p];
    float dx_off = offset[(b * 2 * K2 + 2 * k2 + 1) * NPIX + p];
    float m      = mask  [(b * K2 + k2) * NPIX + p];

    float yf = (float)(ky + ho - 1) + dy_off;
    float xf = (float)(kx + wo - 1) + dx_off;
    float y0f = floorf(yf), x0f = floorf(xf);
    float dy = yf - y0f, dx = xf - x0f;
    int y0 = (int)y0f, x0 = (int)x0f;
    int y1 = y0 + 1,   x1 = x0 + 1;

    float w00 = (1.f - dy) * (1.f - dx) * m;
    float w01 = (1.f - dy) * dx * m;
    float w10 = dy * (1.f - dx) * m;
    float w11 = dy * dx * m;
    bool vy0 = (y0 >= 0) & (y0 < HH), vy1 = (y1 >= 0) & (y1 < HH);
    bool vx0 = (x0 >= 0) & (x0 < WW), vx1 = (x1 >= 0) & (x1 < WW);
    if (!(vy0 & vx0)) w00 = 0.f;
    if (!(vy0 & vx1)) w01 = 0.f;
    if (!(vy1 & vx0)) w10 = 0.f;
    if (!(vy1 & vx1)) w11 = 0.f;

    int y0c = min(max(y0, 0), HH - 1), y1c = min(max(y1, 0), HH - 1);
    int x0c = min(max(x0, 0), WW - 1), x1c = min(max(x1, 0), WW - 1);
    int base = b * NPIX;
    g_sidx[t] = make_int4((base + y0c * WW + x0c) * CIN,
                          (base + y0c * WW + x1c) * CIN,
                          (base + y1c * WW + x0c) * CIN,
                          (base + y1c * WW + x1c) * CIN);
    g_swt[t] = make_float4(w00, w01, w10, w11);
}

// ---------------------------------------------------------------------------
// Main: TF32 mma.sync implicit GEMM. CTA: 128px x 256co, K=2304 in 72 chunks
// of 32 (ci32 outer, k2 inner). 8 warps, warp tile 64x64.
// Double-buffered A(2x18KB)/W(2x36KB) smem, pad-36 rows => conflict-free LDS.
// ---------------------------------------------------------------------------
// floats: A0 0 | A1 4608 | W0 9216 | W1 18432 | (bytes) sO 110592 | sW 129024 | sB 147456
#define SMEM_DYN 148480

__global__ __launch_bounds__(256, 1)
void k_conv(const float* __restrict__ bias, float* __restrict__ out) {
    extern __shared__ float dsm[];
    float*  A_s[2] = { dsm,        dsm + 4608 };
    float*  W_s[2] = { dsm + 9216, dsm + 18432 };   // FIX: stage stride = 9216 floats
    char*   pb  = (char*)dsm;
    int4*   sO9 = (int4*)(pb + 110592);
    float4* sW9 = (float4*)(pb + 129024);
    float*  sB  = (float*)(pb + 147456);

    int tid  = threadIdx.x;
    int b    = blockIdx.x >> 5;
    int p0   = (blockIdx.x & 31) * 128;
    int warp = tid >> 5, lane = tid & 31;

    for (int i = tid; i < 1152; i += 256) {
        int k2 = i >> 7, pl = i & 127;
        int gi = (b * K2 + k2) * NPIX + p0 + pl;
        sO9[i] = g_sidx[gi];
        sW9[i] = g_swt[gi];
    }
    sB[tid] = bias[tid];

    // ---- per-thread mappings ----
    int e = lane & 7, g = lane >> 3;          // A-build: ci4 slot, px slot
    int ty = lane >> 2, tk = lane & 3;        // mma frag coords
    int wm = warp >> 2, wn = warp & 3;        // warp tile: px wm*64, co wn*64
    const float4* X = (const float4*)g_xnhwc;

    float acc[4][8][4];
#pragma unroll
    for (int i = 0; i < 4; i++)
#pragma unroll
        for (int j = 0; j < 8; j++)
#pragma unroll
            for (int q = 0; q < 4; q++) acc[i][j][q] = 0.f;

    // ---- builders ----
    auto build_W = [&](int ch, int s) {
        const char* src = (const char*)(g_wt + ch * 8192);
        uint32_t dst = smem_u32(W_s[s]);
#pragma unroll
        for (int i = 0; i < 8; i++) {
            int lin = tid + i * 256;             // 0..2047
            int co = lin >> 3, j = lin & 7;      // 16B segment j of row co
            uint32_t d = dst + (uint32_t)(co * 144 + j * 16);
            const char* gp = src + (size_t)lin * 16;
            asm volatile("cp.async.cg.shared.global [%0], [%1], 16;" :: "r"(d), "l"(gp));
        }
        asm volatile("cp.async.commit_group;" ::: "memory");
    };
    auto build_A = [&](int ch, int s) {
        int c32 = ch / 9, k2 = ch - c32 * 9;
        int ci4 = c32 * 8 + e;
        char* abuf = (char*)A_s[s];
#pragma unroll
        for (int r = 0; r < 4; r++) {
            int pl = warp * 16 + r * 4 + g;
            int4   o  = sO9[(k2 << 7) + pl];
            float4 wt = sW9[(k2 << 7) + pl];
            float4 v00 = __ldg(&X[(o.x >> 2) + ci4]);
            float4 v01 = __ldg(&X[(o.y >> 2) + ci4]);
            float4 v10 = __ldg(&X[(o.z >> 2) + ci4]);
            float4 v11 = __ldg(&X[(o.w >> 2) + ci4]);
            uint4 t;
            t.x = f2tf32(wt.x * v00.x + wt.y * v01.x + wt.z * v10.x + wt.w * v11.x);
            t.y = f2tf32(wt.x * v00.y + wt.y * v01.y + wt.z * v10.y + wt.w * v11.y);
            t.z = f2tf32(wt.x * v00.z + wt.y * v01.z + wt.z * v10.z + wt.w * v11.z);
            t.w = f2tf32(wt.x * v00.w + wt.y * v01.w + wt.z * v10.w + wt.w * v11.w);
            *(uint4*)(abuf + pl * 144 + e * 16) = t;
        }
    };

    // ---- prologue: build chunk 0 ----
    __syncthreads();           // sO9/sW9/sB ready
    build_W(0, 0);
    build_A(0, 0);
    asm volatile("cp.async.wait_group 0;" ::: "memory");
    __syncthreads();

    for (int ch = 0; ch < NCHUNK; ch++) {
        int s = ch & 1;
        if (ch + 1 < NCHUNK) build_W(ch + 1, s ^ 1);

        // ---- mma on buffer s ----
        const float* As = A_s[s] + (wm * 64 + ty) * PAD + tk;
        const float* Ws = W_s[s] + (wn * 64 + ty) * PAD + tk;
#pragma unroll
        for (int ks = 0; ks < 4; ks++) {
            uint32_t a[4][4], bb[8][2];
#pragma unroll
            for (int i = 0; i < 4; i++) {
                const float* ap = As + i * 16 * PAD + ks * 8;
                a[i][0] = __float_as_uint(ap[0]);
                a[i][1] = __float_as_uint(ap[8 * PAD]);
                a[i][2] = __float_as_uint(ap[4]);
                a[i][3] = __float_as_uint(ap[8 * PAD + 4]);
            }
#pragma unroll
            for (int j = 0; j < 8; j++) {
                const float* bp = Ws + j * 8 * PAD + ks * 8;
                bb[j][0] = __float_as_uint(bp[0]);
                bb[j][1] = __float_as_uint(bp[4]);
            }
#pragma unroll
            for (int i = 0; i < 4; i++)
#pragma unroll
                for (int j = 0; j < 8; j++)
                    mma_tf32(acc[i][j], a[i], bb[j]);
        }

        if (ch + 1 < NCHUNK) build_A(ch + 1, s ^ 1);
        asm volatile("cp.async.wait_group 0;" ::: "memory");
        __syncthreads();
    }

    // ---- epilogue: bias + store NCHW ----
    float* ob = out + (size_t)b * COUT * NPIX;
#pragma unroll
    for (int j = 0; j < 8; j++) {
        int co = wn * 64 + j * 8 + 2 * tk;
        float b0 = sB[co], b1 = sB[co + 1];
#pragma unroll
        for (int i = 0; i < 4; i++) {
            int px = p0 + wm * 64 + i * 16 + ty;
            ob[(size_t)co * NPIX + px]           = acc[i][j][0] + b0;
            ob[(size_t)(co + 1) * NPIX + px]     = acc[i][j][1] + b1;
            ob[(size_t)co * NPIX + px + 8]       = acc[i][j][2] + b0;
            ob[(size_t)(co + 1) * NPIX + px + 8] = acc[i][j][3] + b1;
        }
    }
}

// ---------------------------------------------------------------------------
// GroupNorm(32) + ReLU in place
__global__ __launch_bounds__(256)
void k_gn(float* __restrict__ out,
          const float* __restrict__ gamma, const float* __restrict__ beta) {
    int b = blockIdx.x >> 5;
    int g = blockIdx.x & 31;
    float4* b4 = (float4*)(out + ((size_t)(b * COUT + g * 8)) * NPIX);
    int tid = threadIdx.x;

    float s = 0.f, ss = 0.f;
    for (int i = tid; i < 8192; i += 256) {
        float4 v = b4[i];
        s  += v.x + v.y + v.z + v.w;
        ss += v.x * v.x + v.y * v.y + v.z * v.z + v.w * v.w;
    }
#pragma unroll
    for (int o = 16; o; o >>= 1) {
        s  += __shfl_down_sync(0xFFFFFFFFu, s, o);
        ss += __shfl_down_sync(0xFFFFFFFFu, ss, o);
    }
    __shared__ float red[16];
    __shared__ float stats[2];
    int warp = tid >> 5, lane = tid & 31;
    if (lane == 0) { red[warp] = s; red[warp + 8] = ss; }
    __syncthreads();
    if (tid == 0) {
        float S = 0.f, SS = 0.f;
#pragma unroll
        for (int i = 0; i < 8; i++) { S += red[i]; SS += red[i + 8]; }
        float mu  = S * (1.f / 32768.f);
        float var = SS * (1.f / 32768.f) - mu * mu;
        stats[0] = mu;
        stats[1] = rsqrtf(var + 1e-5f);
    }
    __syncthreads();
    float mu = stats[0], rstd = stats[1];
    for (int i = tid; i < 8192; i += 256) {
        int c = g * 8 + (i >> 10);
        float ga = gamma[c], be = beta[c];
        float4 v = b4[i];
        v.x = fmaxf((v.x - mu) * rstd * ga + be, 0.f);
        v.y = fmaxf((v.y - mu) * rstd * ga + be, 0.f);
        v.z = fmaxf((v.z - mu) * rstd * ga + be, 0.f);
        v.w = fmaxf((v.w - mu) * rstd * ga + be, 0.f);
        b4[i] = v;
    }
}

// ---------------------------------------------------------------------------
extern "C" void kernel_launch(void* const* d_in, const int* in_sizes, int n_in,
                              void* d_out, int out_size) {
    const float* x      = (const float*)d_in[0];
    const float* offset = (const float*)d_in[1];
    const float* mask   = (const float*)d_in[2];
    const float* weight = (const float*)d_in[3];
    const float* bias   = (const float*)d_in[4];
    const float* gamma  = (const float*)d_in[5];
    const float* beta   = (const float*)d_in[6];
    float* out = (float*)d_out;

    cudaFuncSetAttribute(k_conv, cudaFuncAttributeMaxDynamicSharedMemorySize, SMEM_DYN);

    k_prep_x<<<dim3(128, 8, 4), dim3(32, 8)>>>(x);
    k_prep_w<<<NCHUNK, 256>>>(weight);
    k_prep_params<<<576, 256>>>(offset, mask);
    k_conv<<<128, 256, SMEM_DYN>>>(bias, out);
    k_gn<<<128, 256>>>(out, gamma, beta);
}

// round 5
// speedup vs baseline: 3.0422x; 1.1227x over previous
#include <cuda_runtime.h>
#include <cstdint>

#define B_    4
#define CIN   256
#define HH    64
#define WW    64
#define COUT  256
#define K2    9
#define NPIX  4096
#define NCHUNK 72               // 8 ci32-chunks * 9 k2, order: c32 outer, k2 inner
#define SROW  40                // floats per smem row (160B): conflict-free LDS.64

// ---------------- scratch ----------------
__device__ __align__(16) float    g_xnhwc[B_ * NPIX * CIN];   // x NHWC fp32
__device__ __align__(16) uint32_t g_wt[NCHUNK * 8192];        // W tf32: [ch][co256][k32 permuted]
__device__ __align__(16) int4     g_sidx[B_ * K2 * NPIX];
__device__ __align__(16) float4   g_swt [B_ * K2 * NPIX];

__device__ __forceinline__ uint32_t smem_u32(const void* p) {
    uint32_t a;
    asm("{ .reg .u64 t; cvta.to.shared.u64 t, %1; cvt.u32.u64 %0, t; }" : "=r"(a) : "l"(p));
    return a;
}
__device__ __forceinline__ uint32_t f2tf32(float v) {
    uint32_t t;
    asm("cvt.rna.tf32.f32 %0, %1;" : "=r"(t) : "f"(v));
    return t;
}
__device__ __forceinline__ void mma_tf32(float* c, const uint32_t* a, const uint32_t* b) {
    asm volatile("mma.sync.aligned.m16n8k8.row.col.f32.tf32.tf32.f32 "
        "{%0,%1,%2,%3}, {%4,%5,%6,%7}, {%8,%9}, {%0,%1,%2,%3};"
        : "+f"(c[0]), "+f"(c[1]), "+f"(c[2]), "+f"(c[3])
        : "r"(a[0]), "r"(a[1]), "r"(a[2]), "r"(a[3]), "r"(b[0]), "r"(b[1]));
}

// ---------------------------------------------------------------------------
// Prep 1: x NCHW -> NHWC
__global__ void k_prep_x(const float* __restrict__ x) {
    __shared__ float tile[32][33];
    int b = blockIdx.z, p0 = blockIdx.x * 32, c0 = blockIdx.y * 32;
    int tx = threadIdx.x, ty = threadIdx.y;
#pragma unroll
    for (int i = ty; i < 32; i += 8)
        tile[i][tx] = x[(b * CIN + c0 + i) * NPIX + p0 + tx];
    __syncthreads();
#pragma unroll
    for (int i = ty; i < 32; i += 8)
        g_xnhwc[(b * NPIX + p0 + i) * CIN + c0 + tx] = tile[tx][i];
}

// Prep 2: W -> tf32 chunks [ch][co][k32], k PERMUTED within each 8-group:
// pos = ksg*8 + 2*(kg&3) + (kg>>2). Same permutation applied to A => dot
// product unchanged, but (tk, tk+4) fragment pairs become adjacent (LDS.64).
__global__ void k_prep_w(const float* __restrict__ w) {
    int ch  = blockIdx.x;
    int c32 = ch / 9, k2 = ch - c32 * 9;
    uint32_t* dst = g_wt + ch * 8192;
    for (int e = threadIdx.x; e < 8192; e += 256) {
        int r = e >> 5, j = e & 31;          // co, k-within-chunk
        int kg = j & 7, ksg = j >> 3;
        int pos = ksg * 8 + 2 * (kg & 3) + (kg >> 2);
        float v = w[(r * CIN + c32 * 32 + j) * K2 + k2];
        dst[r * 32 + pos] = f2tf32(v);
    }
}

// Prep 3: sampling params
__global__ void k_prep_params(const float* __restrict__ offset,
                              const float* __restrict__ mask) {
    int t = blockIdx.x * blockDim.x + threadIdx.x;
    int b  = t / (K2 * NPIX);
    int r  = t - b * (K2 * NPIX);
    int k2 = r >> 12;
    int p  = r & (NPIX - 1);
    int ho = p >> 6, wo = p & 63;
    int ky = k2 / 3, kx = k2 - ky * 3;

    float dy_off = offset[(b * 2 * K2 + 2 * k2    ) * NPIX + p];
    float dx_off = offset[(b * 2 * K2 + 2 * k2 + 1) * NPIX + p];
    float m      = mask  [(b * K2 + k2) * NPIX + p];

    float yf = (float)(ky + ho - 1) + dy_off;
    float xf = (float)(kx + wo - 1) + dx_off;
    float y0f = floorf(yf), x0f = floorf(xf);
    float dy = yf - y0f, dx = xf - x0f;
    int y0 = (int)y0f, x0 = (int)x0f;
    int y1 = y0 + 1,   x1 = x0 + 1;

    float w00 = (1.f - dy) * (1.f - dx) * m;
    float w01 = (1.f - dy) * dx * m;
    float w10 = dy * (1.f - dx) * m;
    float w11 = dy * dx * m;
    bool vy0 = (y0 >= 0) & (y0 < HH), vy1 = (y1 >= 0) & (y1 < HH);
    bool vx0 = (x0 >= 0) & (x0 < WW), vx1 = (x1 >= 0) & (x1 < WW);
    if (!(vy0 & vx0)) w00 = 0.f;
    if (!(vy0 & vx1)) w01 = 0.f;
    if (!(vy1 & vx0)) w10 = 0.f;
    if (!(vy1 & vx1)) w11 = 0.f;

    int y0c = min(max(y0, 0), HH - 1), y1c = min(max(y1, 0), HH - 1);
    int x0c = min(max(x0, 0), WW - 1), x1c = min(max(x1, 0), WW - 1);
    int base = b * NPIX;
    g_sidx[t] = make_int4((base + y0c * WW + x0c) * CIN,
                          (base + y0c * WW + x1c) * CIN,
                          (base + y1c * WW + x0c) * CIN,
                          (base + y1c * WW + x1c) * CIN);
    g_swt[t] = make_float4(w00, w01, w10, w11);
}

// ---------------------------------------------------------------------------
// Main: TF32 mma.sync implicit GEMM. CTA: 128px x 256co, K=2304 in 72 chunks.
// 16 warps (block 512), warp tile 64px x 32co, permuted-k layout, LDS.64 frags.
// ---------------------------------------------------------------------------
// floats: A0 0 | A1 5120 | W0 10240 | W1 20480
// bytes:  sO9 122880 | sW9 141312 | sB 159744 | end 160768
#define SMEM_DYN 160768

__global__ __launch_bounds__(512, 1)
void k_conv(const float* __restrict__ bias, float* __restrict__ out) {
    extern __shared__ float dsm[];
    float*  A_s[2] = { dsm,         dsm + 5120 };
    float*  W_s[2] = { dsm + 10240, dsm + 20480 };
    char*   pb  = (char*)dsm;
    int4*   sO9 = (int4*)(pb + 122880);
    float4* sW9 = (float4*)(pb + 141312);
    float*  sB  = (float*)(pb + 159744);

    int tid  = threadIdx.x;
    int b    = blockIdx.x >> 5;
    int p0   = (blockIdx.x & 31) * 128;
    int warp = tid >> 5, lane = tid & 31;

    for (int i = tid; i < 1152; i += 512) {
        int k2 = i >> 7, pl = i & 127;
        int gi = (b * K2 + k2) * NPIX + p0 + pl;
        sO9[i] = g_sidx[gi];
        sW9[i] = g_swt[gi];
    }
    if (tid < 256) sB[tid] = bias[tid];

    // ---- per-thread mappings ----
    int ty = lane >> 2, tk = lane & 3;        // mma frag coords
    int wm = warp >> 3, wn = warp & 7;        // warp tile: px wm*64, co wn*32
    int pl_b = tid >> 2, ksg_b = tid & 3;     // A-build: pixel, k-group-of-8
    const float4* X = (const float4*)g_xnhwc;

    float acc[4][4][4];
#pragma unroll
    for (int i = 0; i < 4; i++)
#pragma unroll
        for (int j = 0; j < 4; j++)
#pragma unroll
            for (int q = 0; q < 4; q++) acc[i][j][q] = 0.f;

    // ---- builders ----
    auto build_W = [&](int ch, int s) {
        const char* src = (const char*)(g_wt + ch * 8192);
        uint32_t dst = smem_u32(W_s[s]);
#pragma unroll
        for (int i = 0; i < 4; i++) {
            int lin = tid + i * 512;             // 0..2047
            int co = lin >> 3, seg = lin & 7;    // 16B segment of row co
            uint32_t d = dst + (uint32_t)(co * 160 + seg * 16);
            const char* gp = src + (size_t)lin * 16;
            asm volatile("cp.async.cg.shared.global [%0], [%1], 16;" :: "r"(d), "l"(gp));
        }
        asm volatile("cp.async.commit_group;" ::: "memory");
    };
    auto build_A = [&](int ch, int s) {
        int c32 = ch / 9, k2 = ch - c32 * 9;
        int ci4 = c32 * 8 + ksg_b * 2;
        int4   o  = sO9[(k2 << 7) + pl_b];
        float4 wt = sW9[(k2 << 7) + pl_b];
        float4 a0 = __ldg(&X[(o.x >> 2) + ci4]), a1 = __ldg(&X[(o.x >> 2) + ci4 + 1]);
        float4 b0 = __ldg(&X[(o.y >> 2) + ci4]), b1 = __ldg(&X[(o.y >> 2) + ci4 + 1]);
        float4 c0 = __ldg(&X[(o.z >> 2) + ci4]), c1 = __ldg(&X[(o.z >> 2) + ci4 + 1]);
        float4 d0 = __ldg(&X[(o.w >> 2) + ci4]), d1 = __ldg(&X[(o.w >> 2) + ci4 + 1]);
        float v0 = wt.x * a0.x + wt.y * b0.x + wt.z * c0.x + wt.w * d0.x;
        float v1 = wt.x * a0.y + wt.y * b0.y + wt.z * c0.y + wt.w * d0.y;
        float v2 = wt.x * a0.z + wt.y * b0.z + wt.z * c0.z + wt.w * d0.z;
        float v3 = wt.x * a0.w + wt.y * b0.w + wt.z * c0.w + wt.w * d0.w;
        float v4 = wt.x * a1.x + wt.y * b1.x + wt.z * c1.x + wt.w * d1.x;
        float v5 = wt.x * a1.y + wt.y * b1.y + wt.z * c1.y + wt.w * d1.y;
        float v6 = wt.x * a1.z + wt.y * b1.z + wt.z * c1.z + wt.w * d1.z;
        float v7 = wt.x * a1.w + wt.y * b1.w + wt.z * c1.w + wt.w * d1.w;
        // permuted order: pos <- k pairs (0,4),(1,5),(2,6),(3,7)
        uint4 s1 = make_uint4(f2tf32(v0), f2tf32(v4), f2tf32(v1), f2tf32(v5));
        uint4 s2 = make_uint4(f2tf32(v2), f2tf32(v6), f2tf32(v3), f2tf32(v7));
        uint4* ab = (uint4*)(A_s[s] + pl_b * SROW + ksg_b * 8);
        ab[0] = s1;
        ab[1] = s2;
    };

    // ---- prologue: build chunk 0 ----
    __syncthreads();           // sO9/sW9/sB ready
    build_W(0, 0);
    build_A(0, 0);
    asm volatile("cp.async.wait_group 0;" ::: "memory");
    __syncthreads();

    for (int ch = 0; ch < NCHUNK; ch++) {
        int s = ch & 1;
        if (ch + 1 < NCHUNK) build_W(ch + 1, s ^ 1);

        // ---- mma on buffer s: all fragment loads are LDS.64 ----
        const float* As = A_s[s] + (wm * 64 + ty) * SROW + 2 * tk;
        const float* Ws = W_s[s] + (wn * 32 + ty) * SROW + 2 * tk;
#pragma unroll
        for (int ks = 0; ks < 4; ks++) {
            float2 al[4], ah[4], bv[4];
#pragma unroll
            for (int i = 0; i < 4; i++) {
                al[i] = *(const float2*)(As + i * (16 * SROW) + ks * 8);
                ah[i] = *(const float2*)(As + i * (16 * SROW) + 8 * SROW + ks * 8);
            }
#pragma unroll
            for (int j = 0; j < 4; j++)
                bv[j] = *(const float2*)(Ws + j * (8 * SROW) + ks * 8);
#pragma unroll
            for (int i = 0; i < 4; i++) {
                uint32_t a[4] = { __float_as_uint(al[i].x), __float_as_uint(ah[i].x),
                                  __float_as_uint(al[i].y), __float_as_uint(ah[i].y) };
#pragma unroll
                for (int j = 0; j < 4; j++) {
                    uint32_t bb[2] = { __float_as_uint(bv[j].x), __float_as_uint(bv[j].y) };
                    mma_tf32(acc[i][j], a, bb);
                }
            }
        }

        if (ch + 1 < NCHUNK) build_A(ch + 1, s ^ 1);
        asm volatile("cp.async.wait_group 0;" ::: "memory");
        __syncthreads();
    }

    // ---- epilogue: bias + store NCHW ----
    float* ob = out + (size_t)b * COUT * NPIX;
#pragma unroll
    for (int j = 0; j < 4; j++) {
        int co = wn * 32 + j * 8 + 2 * tk;
        float b0 = sB[co], b1 = sB[co + 1];
#pragma unroll
        for (int i = 0; i < 4; i++) {
            int px = p0 + wm * 64 + i * 16 + ty;
            ob[(size_t)co * NPIX + px]           = acc[i][j][0] + b0;
            ob[(size_t)(co + 1) * NPIX + px]     = acc[i][j][1] + b1;
            ob[(size_t)co * NPIX + px + 8]       = acc[i][j][2] + b0;
            ob[(size_t)(co + 1) * NPIX + px + 8] = acc[i][j][3] + b1;
        }
    }
}

// ---------------------------------------------------------------------------
// GroupNorm(32) + ReLU in place
__global__ __launch_bounds__(256)
void k_gn(float* __restrict__ out,
          const float* __restrict__ gamma, const float* __restrict__ beta) {
    int b = blockIdx.x >> 5;
    int g = blockIdx.x & 31;
    float4* b4 = (float4*)(out + ((size_t)(b * COUT + g * 8)) * NPIX);
    int tid = threadIdx.x;

    float s = 0.f, ss = 0.f;
    for (int i = tid; i < 8192; i += 256) {
        float4 v = b4[i];
        s  += v.x + v.y + v.z + v.w;
        ss += v.x * v.x + v.y * v.y + v.z * v.z + v.w * v.w;
    }
#pragma unroll
    for (int o = 16; o; o >>= 1) {
        s  += __shfl_down_sync(0xFFFFFFFFu, s, o);
        ss += __shfl_down_sync(0xFFFFFFFFu, ss, o);
    }
    __shared__ float red[16];
    __shared__ float stats[2];
    int warp = tid >> 5, lane = tid & 31;
    if (lane == 0) { red[warp] = s; red[warp + 8] = ss; }
    __syncthreads();
    if (tid == 0) {
        float S = 0.f, SS = 0.f;
#pragma unroll
        for (int i = 0; i < 8; i++) { S += red[i]; SS += red[i + 8]; }
        float mu  = S * (1.f / 32768.f);
        float var = SS * (1.f / 32768.f) - mu * mu;
        stats[0] = mu;
        stats[1] = rsqrtf(var + 1e-5f);
    }
    __syncthreads();
    float mu = stats[0], rstd = stats[1];
    for (int i = tid; i < 8192; i += 256) {
        int c = g * 8 + (i >> 10);
        float ga = gamma[c], be = beta[c];
        float4 v = b4[i];
        v.x = fmaxf((v.x - mu) * rstd * ga + be, 0.f);
        v.y = fmaxf((v.y - mu) * rstd * ga + be, 0.f);
        v.z = fmaxf((v.z - mu) * rstd * ga + be, 0.f);
        v.w = fmaxf((v.w - mu) * rstd * ga + be, 0.f);
        b4[i] = v;
    }
}

// ---------------------------------------------------------------------------
extern "C" void kernel_launch(void* const* d_in, const int* in_sizes, int n_in,
                              void* d_out, int out_size) {
    const float* x      = (const float*)d_in[0];
    const float* offset = (const float*)d_in[1];
    const float* mask   = (const float*)d_in[2];
    const float* weight = (const float*)d_in[3];
    const float* bias   = (const float*)d_in[4];
    const float* gamma  = (const float*)d_in[5];
    const float* beta   = (const float*)d_in[6];
    float* out = (float*)d_out;

    cudaFuncSetAttribute(k_conv, cudaFuncAttributeMaxDynamicSharedMemorySize, SMEM_DYN);

    k_prep_x<<<dim3(128, 8, 4), dim3(32, 8)>>>(x);
    k_prep_w<<<NCHUNK, 256>>>(weight);
    k_prep_params<<<576, 256>>>(offset, mask);
    k_conv<<<128, 512, SMEM_DYN>>>(bias, out);
    k_gn<<<128, 256>>>(out, gamma, beta);
}